// round 16
// baseline (speedup 1.0000x reference)
#include <cuda_runtime.h>
#include <cstdint>

// Correlation cost volume via banded fp16 mma.sync (m16n8k16, fp32 accum),
// persistent blocks, 4-deep cp.async buffer ring at depth 2 -> the mid-step
// barrier is provably redundant and removed; streaming (.cs) output stores.
// out[b,d,h,w] = mean_c( x[b,c,h,w] * y[b,c,h,w-d] ), 0 where w<d (exact via
// zero-padded halo; cp.async zfill).
// Tile = one (b, h, w-tile of 128): A[i,k]=x[k,w0+i] (128x32),
// B[s,k]=y[k,w0-48+s] (176x32), P = A.B^T banded; warp m computes rows
// [16m,16m+16) x cols [16m,16m+64). K streamed in 2 chunks of 16 channels
// (one m16n8k16 step each); accumulators persist across the 2 chunks.
// d = 48-(s-i); epilogue stages to St[48-d][i] so per-d gather is contiguous.
//
// R16 vs R15: NBUF 2 -> 4. Buffer p's refill is issued at the top of step
// p+4, with top-of-step barriers at p+1..p+3 in between, so the kc==0
// end-of-step __syncthreads (which existed only for refill WAR safety at
// NBUF=2) is deleted: 3 barriers per 2 steps instead of 4, and kc0 MMA warps
// flow into kc1 without a reconvergence point. 2 blocks/SM (occupancy 2 vs 3
// measured neutral in R8/R11). Output via st.global.cs (evict-first).

#define BDIM 8
#define CDIM 32
#define HDIM 256
#define WDIM 512
#define MAXD 48

#define MT   128
#define NT   176
#define NTHR 256
#define GRID 296                  // 148 SMs x 2 blocks: one wave
#define NTILES (BDIM * HDIM * (WDIM / MT))   // 8192
#define KC   16                   // channels per pipeline step (one k16 MMA)
#define NBUF 4

#define AP 132                    // A pitch (words): k-pair frag loads conflict-free
#define BP 180                    // B pitch (words): conflict-free
#define SP 136                    // stage pitch (words)
#define A_WORDS (KC * AP)         // 2112
#define B_WORDS (KC * BP)         // 2880
#define BUF_WORDS (A_WORDS + B_WORDS)       // 4992 (~19.5 KB)
#define ST_OFF  (NBUF * BUF_WORDS)          // 19968
#define ST_WORDS ((MAXD + 1) * SP)          // 6664
#define SMEM_BYTES ((ST_OFF + ST_WORDS) * 4)  // 106528 B -> 2 blocks/SM

#define A_CHUNKS (KC * (MT / 4))  // 512 16B chunks per step
#define B_CHUNKS (KC * (NT / 4))  // 704

__device__ __forceinline__ uint32_t pack16(float v0, float v1) {
    uint32_t r;   // f16x2 with lo = v0, hi = v1
    asm("cvt.rn.f16x2.f32 %0, %1, %2;" : "=r"(r) : "f"(v1), "f"(v0));
    return r;
}
__device__ __forceinline__ uint32_t smem_u32(const void* p) {
    uint32_t a;
    asm("{ .reg .u64 t; cvta.to.shared.u64 t, %1; cvt.u32.u64 %0, t; }" : "=r"(a) : "l"(p));
    return a;
}
__device__ __forceinline__ void cp16(uint32_t dst, const void* src, int src_sz) {
    asm volatile("cp.async.cg.shared.global [%0], [%1], 16, %2;"
                 :: "r"(dst), "l"(src), "r"(src_sz) : "memory");
}
__device__ __forceinline__ void mma_f16(float* c, const uint32_t* a,
                                        uint32_t b0, uint32_t b1) {
    asm volatile(
        "mma.sync.aligned.m16n8k16.row.col.f32.f16.f16.f32 "
        "{%0,%1,%2,%3}, {%4,%5,%6,%7}, {%8,%9}, {%0,%1,%2,%3};"
        : "+f"(c[0]), "+f"(c[1]), "+f"(c[2]), "+f"(c[3])
        : "r"(a[0]), "r"(a[1]), "r"(a[2]), "r"(a[3]), "r"(b0), "r"(b1));
}

__global__ __launch_bounds__(NTHR, 2)
void corr_mma(const float* __restrict__ x, const float* __restrict__ y,
              float* __restrict__ out) {
    extern __shared__ float smem[];
    const uint32_t sb = smem_u32(smem);

    const int tid  = threadIdx.x;
    const int warp = tid >> 5, lane = tid & 31;
    const int bid  = blockIdx.x;

    const size_t plane = (size_t)HDIM * WDIM;

    // tiles bid, bid+GRID, ... < NTILES; 2 pipeline steps per tile
    const int ntiles = (NTILES - bid + GRID - 1) / GRID;
    const int nsteps = 2 * ntiles;

    // ---- stage one 16-channel K-chunk of (A,B) for local step ls ----
    auto issue_stage = [&](int ls) {
        const int ti = bid + GRID * (ls >> 1);      // tile id
        const int kc = ls & 1, pb = ls & (NBUF - 1);
        const int w0 = (ti & 3) * MT;
        const int h  = (ti >> 2) & (HDIM - 1);
        const int b  = ti >> 10;
        const float* xr = x + ((size_t)b * CDIM + kc * KC) * plane + (size_t)h * WDIM;
        const float* yr = y + ((size_t)b * CDIM + kc * KC) * plane + (size_t)h * WDIM;
        const uint32_t abase = sb + (pb * BUF_WORDS) * 4;
        const uint32_t bbase = abase + A_WORDS * 4;
        #pragma unroll 2
        for (int i = tid; i < A_CHUNKS + B_CHUNKS; i += NTHR) {
            if (i < A_CHUNKS) {
                const int k = i >> 5, v = (i & 31) << 2;
                cp16(abase + (k * AP + v) * 4, xr + k * plane + w0 + v, 16);
            } else {
                const int j = i - A_CHUNKS;
                const int k = j / (NT / 4), v = (j % (NT / 4)) << 2;
                const int gw = w0 - MAXD + v;
                cp16(bbase + (k * BP + v) * 4,
                     yr + k * plane + (gw >= 0 ? gw : 0), gw >= 0 ? 16 : 0);
            }
        }
    };

    issue_stage(0);
    asm volatile("cp.async.commit_group;" ::: "memory");

    const int i0 = 16 * warp;
    const int r  = lane >> 2;     // 0..7
    const int cq = lane & 3;      // 0..3
    float* St = smem + ST_OFF;

    float acc[8][4];

    for (int ls = 0; ls < nsteps; ls++) {
        const int kc = ls & 1;
        const int p  = ls & (NBUF - 1);

        // depth-2: issue next step's copy first (hides behind this full step).
        // WAR safety of the issue targeting buf (ls+1)%4: its previous readers
        // ran at step ls-3; top-of-step barriers at ls-2, ls-1, ls lie between.
        if (ls + 1 < nsteps) {
            issue_stage(ls + 1);
            asm volatile("cp.async.commit_group;" ::: "memory");
            asm volatile("cp.async.wait_group 1;" ::: "memory");
        } else {
            asm volatile("cp.async.wait_group 0;" ::: "memory");
        }
        __syncthreads();   // buffer p's data visible to all threads

        if (kc == 0) {
            #pragma unroll
            for (int t = 0; t < 8; t++)
                #pragma unroll
                for (int q = 0; q < 4; q++) acc[t][q] = 0.f;
        }

        // ---- banded MMA: one m16n8k16 step over this 16-channel chunk ----
        const float* As = smem + p * BUF_WORDS;   // [KC][AP] fp32
        const float* Bs = As + A_WORDS;           // [KC][BP] fp32

        uint32_t a[4];
        a[0] = pack16(As[(2 * cq)     * AP + i0 + r],     As[(2 * cq + 1) * AP + i0 + r]);
        a[1] = pack16(As[(2 * cq)     * AP + i0 + r + 8], As[(2 * cq + 1) * AP + i0 + r + 8]);
        a[2] = pack16(As[(2 * cq + 8) * AP + i0 + r],     As[(2 * cq + 9) * AP + i0 + r]);
        a[3] = pack16(As[(2 * cq + 8) * AP + i0 + r + 8], As[(2 * cq + 9) * AP + i0 + r + 8]);

        #pragma unroll
        for (int t = 0; t < 8; t++) {
            const int s0 = i0 + 8 * t;
            uint32_t b0 = pack16(Bs[(2 * cq)     * BP + s0 + r], Bs[(2 * cq + 1) * BP + s0 + r]);
            uint32_t b1 = pack16(Bs[(2 * cq + 8) * BP + s0 + r], Bs[(2 * cq + 9) * BP + s0 + r]);
            mma_f16(acc[t], a, b0, b1);
        }

        // NOTE: no end-of-step barrier on kc==0 (NBUF=4 makes it redundant).

        if (kc == 1) {
            // ---- scatter into shift-normalized stage St[u = 48-d][i] ----
            // St WAR vs previous gather (2 steps ago): top-of-step barriers
            // at ls-1 and ls lie between.
            #pragma unroll
            for (int t = 0; t < 8; t++) {
                #pragma unroll
                for (int q = 0; q < 4; q++) {
                    const int re = r + (q >= 2 ? 8 : 0);
                    const int sl = 8 * t + 2 * cq + (q & 1);
                    const int u  = sl - re;
                    if (u >= 1 && u <= MAXD)
                        St[u * SP + i0 + re] = acc[t][q];
                }
            }
            __syncthreads();

            // ---- gather row u = 48-d (contiguous) + streaming STG.128 ----
            const int ti = bid + GRID * (ls >> 1);
            const int w0 = (ti & 3) * MT;
            const int h  = (ti >> 2) & (HDIM - 1);
            const int b  = ti >> 10;
            const float scale = 1.0f / (float)CDIM;
            const int iq = 4 * lane;
            #pragma unroll
            for (int k = 0; k < 6; k++) {
                const int d = warp + 8 * k;
                float4 v = *reinterpret_cast<const float4*>(&St[(MAXD - d) * SP + iq]);
                v.x *= scale; v.y *= scale; v.z *= scale; v.w *= scale;
                __stcs(reinterpret_cast<float4*>(
                    out + (((size_t)b * MAXD + d) * HDIM + h) * WDIM + w0 + iq), v);
            }
        }
    }
}

extern "C" void kernel_launch(void* const* d_in, const int* in_sizes, int n_in,
                              void* d_out, int out_size) {
    const float* x = (const float*)d_in[0];
    const float* y = (const float*)d_in[1];
    float* out = (float*)d_out;

    cudaFuncSetAttribute(corr_mma,
                         cudaFuncAttributeMaxDynamicSharedMemorySize, SMEM_BYTES);

    corr_mma<<<GRID, NTHR, SMEM_BYTES>>>(x, y, out);
}

// round 17
// speedup vs baseline: 1.0956x; 1.0956x over previous
#include <cuda_runtime.h>
#include <cstdint>

// Correlation cost volume via banded fp16 mma.sync (m16n8k16, fp32 accum),
// persistent blocks (one wave), cp.async double-buffered pipeline continuous
// across tile boundaries; 3 blocks/SM.
// out[b,d,h,w] = mean_c( x[b,c,h,w] * y[b,c,h,w-d] ), 0 where w<d (exact via
// zero-padded halo; cp.async zfill).
// Tile = one (b, h, w-tile of 128): A[i,k]=x[k,w0+i] (128x32),
// B[s,k]=y[k,w0-48+s] (176x32), P = A.B^T banded; warp m computes rows
// [16m,16m+16) x cols [16m,16m+64). K streamed in 2 chunks of 16 channels
// (one m16n8k16 step each); accumulators persist across the 2 chunks.
// d = 48-(s-i); epilogue stages to St[48-d][i] so per-d gather is contiguous.
//
// R17 vs R15 (best, 87.1us): GRID 444 -> 456 (GB300 has 152 SMs; 456 = 152x3
// balances exactly 3 blocks per SM, removing the ~3% straggler tail) and
// streaming .cs output stores (192 MB write-once stream stops evicting the
// y-halo L2 window shared by concurrently-running adjacent-w blocks).
// Pipeline, numerics, layouts byte-identical to R15 (rel_err 2.936685e-4).

#define BDIM 8
#define CDIM 32
#define HDIM 256
#define WDIM 512
#define MAXD 48

#define MT   128
#define NT   176
#define NTHR 256
#define GRID 456                  // 152 SMs x 3 blocks: one balanced wave
#define NTILES (BDIM * HDIM * (WDIM / MT))   // 8192
#define KC   16                   // channels per pipeline step (one k16 MMA)

#define AP 132                    // A pitch (words): k-pair frag loads conflict-free
#define BP 180                    // B pitch (words): conflict-free
#define SP 136                    // stage pitch (words)
#define A_WORDS (KC * AP)         // 2112
#define B_WORDS (KC * BP)         // 2880
#define BUF_WORDS (A_WORDS + B_WORDS)       // 4992 (~19.5 KB)
#define ST_OFF  (2 * BUF_WORDS)             // 9984
#define ST_WORDS ((MAXD + 1) * SP)          // 6664
#define SMEM_BYTES ((ST_OFF + ST_WORDS) * 4)  // 66592 B -> 3 blocks/SM

#define A_CHUNKS (KC * (MT / 4))  // 512 16B chunks per step
#define B_CHUNKS (KC * (NT / 4))  // 704

__device__ __forceinline__ uint32_t pack16(float v0, float v1) {
    uint32_t r;   // f16x2 with lo = v0, hi = v1
    asm("cvt.rn.f16x2.f32 %0, %1, %2;" : "=r"(r) : "f"(v1), "f"(v0));
    return r;
}
__device__ __forceinline__ uint32_t smem_u32(const void* p) {
    uint32_t a;
    asm("{ .reg .u64 t; cvta.to.shared.u64 t, %1; cvt.u32.u64 %0, t; }" : "=r"(a) : "l"(p));
    return a;
}
__device__ __forceinline__ void cp16(uint32_t dst, const void* src, int src_sz) {
    asm volatile("cp.async.cg.shared.global [%0], [%1], 16, %2;"
                 :: "r"(dst), "l"(src), "r"(src_sz) : "memory");
}
__device__ __forceinline__ void mma_f16(float* c, const uint32_t* a,
                                        uint32_t b0, uint32_t b1) {
    asm volatile(
        "mma.sync.aligned.m16n8k16.row.col.f32.f16.f16.f32 "
        "{%0,%1,%2,%3}, {%4,%5,%6,%7}, {%8,%9}, {%0,%1,%2,%3};"
        : "+f"(c[0]), "+f"(c[1]), "+f"(c[2]), "+f"(c[3])
        : "r"(a[0]), "r"(a[1]), "r"(a[2]), "r"(a[3]), "r"(b0), "r"(b1));
}

__global__ __launch_bounds__(NTHR, 3)
void corr_mma(const float* __restrict__ x, const float* __restrict__ y,
              float* __restrict__ out) {
    extern __shared__ float smem[];
    const uint32_t sb = smem_u32(smem);

    const int tid  = threadIdx.x;
    const int warp = tid >> 5, lane = tid & 31;
    const int bid  = blockIdx.x;

    const size_t plane = (size_t)HDIM * WDIM;

    // tiles bid, bid+GRID, ... < NTILES; 2 pipeline steps per tile
    const int ntiles = (NTILES - bid + GRID - 1) / GRID;
    const int nsteps = 2 * ntiles;

    // ---- stage one 16-channel K-chunk of (A,B) for local step ls ----
    auto issue_stage = [&](int ls) {
        const int ti = bid + GRID * (ls >> 1);      // tile id
        const int kc = ls & 1, pb = ls & 1;
        const int w0 = (ti & 3) * MT;
        const int h  = (ti >> 2) & (HDIM - 1);
        const int b  = ti >> 10;
        const float* xr = x + ((size_t)b * CDIM + kc * KC) * plane + (size_t)h * WDIM;
        const float* yr = y + ((size_t)b * CDIM + kc * KC) * plane + (size_t)h * WDIM;
        const uint32_t abase = sb + (pb * BUF_WORDS) * 4;
        const uint32_t bbase = abase + A_WORDS * 4;
        #pragma unroll 2
        for (int i = tid; i < A_CHUNKS + B_CHUNKS; i += NTHR) {
            if (i < A_CHUNKS) {
                const int k = i >> 5, v = (i & 31) << 2;
                cp16(abase + (k * AP + v) * 4, xr + k * plane + w0 + v, 16);
            } else {
                const int j = i - A_CHUNKS;
                const int k = j / (NT / 4), v = (j % (NT / 4)) << 2;
                const int gw = w0 - MAXD + v;
                cp16(bbase + (k * BP + v) * 4,
                     yr + k * plane + (gw >= 0 ? gw : 0), gw >= 0 ? 16 : 0);
            }
        }
    };

    issue_stage(0);
    asm volatile("cp.async.commit_group;" ::: "memory");

    const int i0 = 16 * warp;
    const int r  = lane >> 2;     // 0..7
    const int cq = lane & 3;      // 0..3
    float* St = smem + ST_OFF;

    float acc[8][4];

    for (int ls = 0; ls < nsteps; ls++) {
        const int kc = ls & 1;
        const int p  = ls & 1;

        // depth-2: issue next step's copy first (hides behind this full step).
        // Safe: its buffer's last readers (step ls-1 MMA) are behind the
        // end-of-step barrier every step executes.
        if (ls + 1 < nsteps) {
            issue_stage(ls + 1);
            asm volatile("cp.async.commit_group;" ::: "memory");
            asm volatile("cp.async.wait_group 1;" ::: "memory");
        } else {
            asm volatile("cp.async.wait_group 0;" ::: "memory");
        }
        __syncthreads();   // buffer p's data visible to all threads

        if (kc == 0) {
            #pragma unroll
            for (int t = 0; t < 8; t++)
                #pragma unroll
                for (int q = 0; q < 4; q++) acc[t][q] = 0.f;
        }

        // ---- banded MMA: one m16n8k16 step over this 16-channel chunk ----
        const float* As = smem + p * BUF_WORDS;   // [KC][AP] fp32
        const float* Bs = As + A_WORDS;           // [KC][BP] fp32

        uint32_t a[4];
        a[0] = pack16(As[(2 * cq)     * AP + i0 + r],     As[(2 * cq + 1) * AP + i0 + r]);
        a[1] = pack16(As[(2 * cq)     * AP + i0 + r + 8], As[(2 * cq + 1) * AP + i0 + r + 8]);
        a[2] = pack16(As[(2 * cq + 8) * AP + i0 + r],     As[(2 * cq + 9) * AP + i0 + r]);
        a[3] = pack16(As[(2 * cq + 8) * AP + i0 + r + 8], As[(2 * cq + 9) * AP + i0 + r + 8]);

        #pragma unroll
        for (int t = 0; t < 8; t++) {
            const int s0 = i0 + 8 * t;
            uint32_t b0 = pack16(Bs[(2 * cq)     * BP + s0 + r], Bs[(2 * cq + 1) * BP + s0 + r]);
            uint32_t b1 = pack16(Bs[(2 * cq + 8) * BP + s0 + r], Bs[(2 * cq + 9) * BP + s0 + r]);
            mma_f16(acc[t], a, b0, b1);
        }

        if (kc == 0) {
            __syncthreads();   // end-of-step barrier (orders MMA reads before
                               // this buffer's refill issued at step ls+2)
        } else {
            // ---- scatter into shift-normalized stage St[u = 48-d][i] ----
            #pragma unroll
            for (int t = 0; t < 8; t++) {
                #pragma unroll
                for (int q = 0; q < 4; q++) {
                    const int re = r + (q >= 2 ? 8 : 0);
                    const int sl = 8 * t + 2 * cq + (q & 1);
                    const int u  = sl - re;
                    if (u >= 1 && u <= MAXD)
                        St[u * SP + i0 + re] = acc[t][q];
                }
            }
            __syncthreads();   // doubles as end-of-step barrier

            // ---- gather row u = 48-d (contiguous) + streaming STG.128 ----
            const int ti = bid + GRID * (ls >> 1);
            const int w0 = (ti & 3) * MT;
            const int h  = (ti >> 2) & (HDIM - 1);
            const int b  = ti >> 10;
            const float scale = 1.0f / (float)CDIM;
            const int iq = 4 * lane;
            #pragma unroll
            for (int k = 0; k < 6; k++) {
                const int d = warp + 8 * k;
                float4 v = *reinterpret_cast<const float4*>(&St[(MAXD - d) * SP + iq]);
                v.x *= scale; v.y *= scale; v.z *= scale; v.w *= scale;
                __stcs(reinterpret_cast<float4*>(
                    out + (((size_t)b * MAXD + d) * HDIM + h) * WDIM + w0 + iq), v);
            }
            // St WAR vs next scatter: 2 steps away, barriers in between.
        }
    }
}

extern "C" void kernel_launch(void* const* d_in, const int* in_sizes, int n_in,
                              void* d_out, int out_size) {
    const float* x = (const float*)d_in[0];
    const float* y = (const float*)d_in[1];
    float* out = (float*)d_out;

    cudaFuncSetAttribute(corr_mma,
                         cudaFuncAttributeMaxDynamicSharedMemorySize, SMEM_BYTES);

    corr_mma<<<GRID, NTHR, SMEM_BYTES>>>(x, y, out);
}